// round 1
// baseline (speedup 1.0000x reference)
#include <cuda_runtime.h>
#include <math.h>

// ---------------------------------------------------------------------------
// Problem constants
//   B=256, L=256, V=14, EMB=512, pooled length NH = 128
//   105 = number of unordered token pairs from V=14
// ---------------------------------------------------------------------------
#define NPAIR 105

// ---------------------------------------------------------------------------
// Scratch (static __device__ globals; no allocation at runtime)
// ---------------------------------------------------------------------------
__device__ __align__(16) float g_cwT[2][512 * 768];          // [br][i*768 + kh*256 + o]
__device__ __align__(16) float g_pp[2][NPAIR * 512];         // pooled pair embeddings
__device__ __align__(16) float g_Cp[2][NPAIR * 768];         // Cpair[p][kh*256+o]
__device__ __align__(16) float g_E[2][NPAIR * 128 * 128];    // E[p][h][j]
__device__ int              g_pIdx[2][256 * 128];            // pair index per (b,h)
__device__ float            g_part[256 * 128];               // bias partials (reused)
__device__ float            g_bias[2][128];                  // conv-bias folded through linear
__device__ float            g_eout[256 * 128];               // enemy softmax output
__device__ float            g_f1[256 * 128];                 // friend branch output
__device__ float            g_W[3 * 64 * 128];               // manip conv weight sums (h0/int/hE)
__device__ float            g_A[3 * 64 * 256];               // manip lin reduced (h0/int/hE)

__device__ __forceinline__ int pair_idx(int a, int b) {
    int lo = a < b ? a : b;
    int hi = a < b ? b : a;
    return lo * 14 - (lo * (lo - 1)) / 2 + (hi - lo);
}

// ---------------------------------------------------------------------------
// 1. Transpose conv weights (kw=1 slice): cwT[i*768 + kh*256 + o] = cw[o,i,kh,1]
// ---------------------------------------------------------------------------
__global__ void k_cwT(const float* __restrict__ cw, int br) {
    int tid = blockIdx.x * blockDim.x + threadIdx.x;
    if (tid >= 512 * 768) return;
    int i = tid / 768;
    int r = tid % 768;
    int kh = r >> 8;
    int o  = r & 255;
    g_cwT[br][tid] = cw[((o * 512 + i) * 3 + kh) * 3 + 1];
}

// ---------------------------------------------------------------------------
// 2. Pooled pair embeddings: pp[p][i] = max(emb[t1,i], emb[t2,i])
// ---------------------------------------------------------------------------
__global__ void k_pp(const float* __restrict__ emb, int br) {
    int p = blockIdx.x;
    int t1 = 0, rem = p;
    while (rem >= 14 - t1) { rem -= 14 - t1; t1++; }
    int t2 = t1 + rem;
    int i = threadIdx.x;
    g_pp[br][p * 512 + i] = fmaxf(emb[t1 * 512 + i], emb[t2 * 512 + i]);
}

// ---------------------------------------------------------------------------
// 3. Cpair[p][c] = sum_i pp[p][i] * cwT[i][c]   (105 x 768, K=512)
// ---------------------------------------------------------------------------
__global__ void k_cpair(int br) {
    __shared__ float s[512];
    int p = blockIdx.x, c = threadIdx.x;
    if (c < 512) s[c] = g_pp[br][p * 512 + c];
    __syncthreads();
    const float* ct = g_cwT[br] + c;
    float acc = 0.f;
#pragma unroll 8
    for (int i = 0; i < 512; i++) acc += s[i] * ct[i * 768];
    g_Cp[br][p * 768 + c] = acc;
}

// ---------------------------------------------------------------------------
// 4. Pair indices for enemy branch from input tokens
// ---------------------------------------------------------------------------
__global__ void k_pidx_x(const int* __restrict__ x) {
    int tid = blockIdx.x * blockDim.x + threadIdx.x;
    if (tid >= 256 * 128) return;
    int b = tid >> 7, h = tid & 127;
    g_pIdx[0][tid] = pair_idx(x[b * 256 + 2 * h], x[b * 256 + 2 * h + 1]);
}

// ---------------------------------------------------------------------------
// 5. Conv bias folded through linear: bias[j] = sum_{o,h} cb[o]*lin[o*128+h, j]
// ---------------------------------------------------------------------------
__global__ void k_bias1(const float* __restrict__ cb, const float* __restrict__ lin) {
    int o = blockIdx.x, j = threadIdx.x;
    const float* L = lin + (o << 7) * 128 + j;
    float s = 0.f;
#pragma unroll 4
    for (int h = 0; h < 128; h++) s += L[h * 128];
    g_part[o * 128 + j] = cb[o] * s;
}
__global__ void k_bias2(int br) {
    int j = threadIdx.x;
    float s = 0.f;
    for (int o = 0; o < 256; o++) s += g_part[o * 128 + j];
    g_bias[br][j] = s;
}

// ---------------------------------------------------------------------------
// 6. E-table SGEMM.  Per block: fixed h' (grid.x=128), computes
//    E[p, h', j] = sum_{kh,o valid} Cpair[p][kh*256+o] * lin[(o*128 + h'+1-kh)*128 + j]
//    M=128(p, 105 live), N=128(j), K=768.  256 thr, 8x8 microtile, BK=16.
// ---------------------------------------------------------------------------
__global__ void __launch_bounds__(256) k_egemm(const float* __restrict__ lin, int br) {
    const int hp = blockIdx.x;
    __shared__ float As[16][132];
    __shared__ float Bs[16][132];
    const float* Cp = g_Cp[br];
    float acc[8][8];
#pragma unroll
    for (int i = 0; i < 8; i++)
#pragma unroll
        for (int j = 0; j < 8; j++) acc[i][j] = 0.f;

    const int t = threadIdx.x, tx = t & 15, ty = t >> 4;

    for (int k0 = 0; k0 < 768; k0 += 16) {
        // A tile: 128p x 16k, float4 along k
#pragma unroll
        for (int s = 0; s < 2; s++) {
            int v = t + s * 256;
            int p = v >> 2;
            int kq = (v & 3) << 2;
            float4 a4 = make_float4(0.f, 0.f, 0.f, 0.f);
            if (p < NPAIR) a4 = *(const float4*)(Cp + p * 768 + k0 + kq);
            As[kq + 0][p] = a4.x;
            As[kq + 1][p] = a4.y;
            As[kq + 2][p] = a4.z;
            As[kq + 3][p] = a4.w;
        }
        // B tile: 16k x 128j, generated from lin with the (kh,h') shift
#pragma unroll
        for (int s = 0; s < 2; s++) {
            int v = t + s * 256;
            int kr = v >> 5;
            int jq = (v & 31) << 2;
            int k = k0 + kr;
            int kh = k >> 8, o = k & 255;
            int h = hp + 1 - kh;
            float4 b4 = make_float4(0.f, 0.f, 0.f, 0.f);
            if ((unsigned)h < 128u) b4 = *(const float4*)(lin + ((o << 7) + h) * 128 + jq);
            *(float4*)&Bs[kr][jq] = b4;
        }
        __syncthreads();
#pragma unroll
        for (int kk = 0; kk < 16; kk++) {
            float a[8], b[8];
#pragma unroll
            for (int i = 0; i < 8; i++) a[i] = As[kk][ty * 8 + i];
#pragma unroll
            for (int j = 0; j < 8; j++) b[j] = Bs[kk][tx * 8 + j];
#pragma unroll
            for (int i = 0; i < 8; i++)
#pragma unroll
                for (int j = 0; j < 8; j++) acc[i][j] += a[i] * b[j];
        }
        __syncthreads();
    }

    float* E = g_E[br];
#pragma unroll
    for (int i = 0; i < 8; i++) {
        int p = ty * 8 + i;
        if (p < NPAIR) {
            float* dst = E + ((p << 7) + hp) * 128 + tx * 8;
            *(float4*)dst       = make_float4(acc[i][0], acc[i][1], acc[i][2], acc[i][3]);
            *(float4*)(dst + 4) = make_float4(acc[i][4], acc[i][5], acc[i][6], acc[i][7]);
        }
    }
}

// ---------------------------------------------------------------------------
// 7. Gather-sum (+ optional softmax): logit[b,j] = bias + linb + sum_h E[p(b,h),h,j]
//    SOFTMAX=true -> enemy output (g_eout); false -> friend (g_f1)
// ---------------------------------------------------------------------------
template <bool SOFTMAX>
__global__ void k_gather(const float* __restrict__ linb) {
    int b = blockIdx.x, j = threadIdx.x;
    __shared__ int sp[128];
    __shared__ float red[128];
    const int br = SOFTMAX ? 0 : 1;
    sp[j] = g_pIdx[br][b * 128 + j];
    __syncthreads();
    const float* E = g_E[br];
    float acc = g_bias[br][j] + linb[j];
#pragma unroll 4
    for (int h = 0; h < 128; h++) acc += E[((sp[h] << 7) + h) * 128 + j];

    if (!SOFTMAX) {
        g_f1[b * 128 + j] = acc;
        return;
    }
    red[j] = acc;
    __syncthreads();
    for (int s = 64; s > 0; s >>= 1) {
        if (j < s) red[j] = fmaxf(red[j], red[j + s]);
        __syncthreads();
    }
    float m = red[0];
    __syncthreads();
    float e = expf(acc - m);
    red[j] = e;
    __syncthreads();
    for (int s = 64; s > 0; s >>= 1) {
        if (j < s) red[j] += red[j + s];
        __syncthreads();
    }
    g_eout[b * 128 + j] = e / red[0];
}

// ---------------------------------------------------------------------------
// 8. Manipulator weight precompute:
//    W[v][o][i] over kh subsets; A[v][o][j] = manip_lin reduced over h rows.
// ---------------------------------------------------------------------------
__global__ void k_wsum(const float* __restrict__ mw) {
    int tid = blockIdx.x * blockDim.x + threadIdx.x;
    if (tid >= 3 * 64 * 128) return;
    int v = tid / 8192, r = tid & 8191, o = r >> 7, i = r & 127;
    int base = ((o * 128 + i) * 3) * 3 + 1;  // (o,i,kh=0,kw=1); kh stride = 3
    float w0 = mw[base], w1 = mw[base + 3], w2 = mw[base + 6];
    float s = (v == 0) ? (w1 + w2) : (v == 1 ? (w0 + w1 + w2) : (w0 + w1));
    g_W[tid] = s;
}

__global__ void k_areduce(const float* __restrict__ ml) {
    int o = blockIdx.x, j = threadIdx.x;
    const float* base = ml + (o << 7) * 256 + j;
    float a0 = base[0];
    float ae = base[127 * 256];
    float ai = 0.f;
#pragma unroll 4
    for (int h = 1; h < 127; h++) ai += base[h * 256];
    g_A[0 * 16384 + o * 256 + j] = a0;
    g_A[1 * 16384 + o * 256 + j] = ai;
    g_A[2 * 16384 + o * 256 + j] = ae;
}

// ---------------------------------------------------------------------------
// 9. Manipulator main + friend token/pair generation (fused).
// ---------------------------------------------------------------------------
__global__ void k_manip(const float* __restrict__ mb, const float* __restrict__ mlb) {
    int b = blockIdx.x, t = threadIdx.x;
    __shared__ float eo[128];
    __shared__ float ry[192];
    __shared__ int tok[256];
    if (t < 128) eo[t] = g_eout[b * 128 + t];
    __syncthreads();
    if (t < 192) {
        int v = t >> 6, o = t & 63;
        const float* W = g_W + v * 8192 + o * 128;
        float s = mb[o];
#pragma unroll 4
        for (int i = 0; i < 128; i++) s += eo[i] * W[i];
        ry[t] = fmaxf(s, 0.f);
    }
    __syncthreads();
    int j = t;
    float acc = mlb[j];
#pragma unroll 2
    for (int o = 0; o < 64; o++) {
        acc += ry[o]       * g_A[o * 256 + j]
             + ry[64 + o]  * g_A[16384 + o * 256 + j]
             + ry[128 + o] * g_A[32768 + o * 256 + j];
    }
    tok[j] = (int)(((long long)floorf(fabsf(acc) * 100.0f)) % 14);
    __syncthreads();
    if (t < 128) g_pIdx[1][b * 128 + t] = pair_idx(tok[2 * t], tok[2 * t + 1]);
}

// ---------------------------------------------------------------------------
// 10. Final head: out[b,v] = softmax_v(f1[b] @ L2 + b2)
// ---------------------------------------------------------------------------
__global__ void k_head(const float* __restrict__ L2, const float* __restrict__ b2,
                       float* __restrict__ out) {
    int b = blockIdx.x, v = threadIdx.x;  // 32 threads
    float acc = -INFINITY;
    if (v < 14) {
        acc = b2[v];
        const float* f = g_f1 + b * 128;
#pragma unroll 4
        for (int i = 0; i < 128; i++) acc += f[i] * L2[i * 14 + v];
    }
    float m = acc;
    for (int off = 16; off; off >>= 1) m = fmaxf(m, __shfl_xor_sync(0xffffffffu, m, off));
    float e = (v < 14) ? expf(acc - m) : 0.f;
    float s = e;
    for (int off = 16; off; off >>= 1) s += __shfl_xor_sync(0xffffffffu, s, off);
    if (v < 14) out[b * 14 + v] = e / s;
}

// ---------------------------------------------------------------------------
// Launch sequence (graph-capturable: kernel launches only)
// ---------------------------------------------------------------------------
extern "C" void kernel_launch(void* const* d_in, const int* in_sizes, int n_in,
                              void* d_out, int out_size) {
    (void)in_sizes; (void)n_in; (void)out_size;
    const int*   x    = (const int*)  d_in[0];
    const float* eemb = (const float*)d_in[1];
    const float* ecw  = (const float*)d_in[2];
    const float* ecb  = (const float*)d_in[3];
    const float* elw  = (const float*)d_in[4];
    const float* elb  = (const float*)d_in[5];
    // d_in[6] = rand_proj: dead input (fog_of_war perm == arange)
    const float* mcw  = (const float*)d_in[7];
    const float* mcb  = (const float*)d_in[8];
    const float* mlw  = (const float*)d_in[9];
    const float* mlb  = (const float*)d_in[10];
    const float* femb = (const float*)d_in[11];
    const float* fcw  = (const float*)d_in[12];
    const float* fcb  = (const float*)d_in[13];
    const float* flw  = (const float*)d_in[14];
    const float* flb  = (const float*)d_in[15];
    const float* fl2w = (const float*)d_in[16];
    const float* fl2b = (const float*)d_in[17];
    float* out = (float*)d_out;

    // Weight-only precompute (both branches + manipulator)
    k_cwT<<<1536, 256>>>(ecw, 0);
    k_cwT<<<1536, 256>>>(fcw, 1);
    k_pp<<<NPAIR, 512>>>(eemb, 0);
    k_pp<<<NPAIR, 512>>>(femb, 1);
    k_cpair<<<NPAIR, 768>>>(0);
    k_cpair<<<NPAIR, 768>>>(1);
    k_bias1<<<256, 128>>>(ecb, elw);
    k_bias2<<<1, 128>>>(0);
    k_bias1<<<256, 128>>>(fcb, flw);
    k_bias2<<<1, 128>>>(1);
    k_wsum<<<96, 256>>>(mcw);
    k_areduce<<<64, 256>>>(mlw);

    // Enemy branch
    k_pidx_x<<<128, 256>>>(x);
    k_egemm<<<128, 256>>>(elw, 0);
    k_gather<true><<<256, 128>>>(elb);

    // Manipulator -> friend tokens/pairs
    k_manip<<<256, 256>>>(mcb, mlb);

    // Friend branch
    k_egemm<<<128, 256>>>(flw, 1);
    k_gather<false><<<256, 128>>>(flb);

    // Head
    k_head<<<256, 32>>>(fl2w, fl2b, out);
}

// round 2
// speedup vs baseline: 1.0804x; 1.0804x over previous
#include <cuda_runtime.h>
#include <math.h>

// ---------------------------------------------------------------------------
// B=256, L=256, V=14, EMB=512, pooled length NH=128, NPAIR = C(14,2)+14 = 105
// ---------------------------------------------------------------------------
#define NPAIR 105
typedef unsigned long long ull;

// ---------------------------------------------------------------------------
// Scratch (__device__ globals; no runtime allocation)
// ---------------------------------------------------------------------------
__device__ __align__(16) float g_cwT[2][512 * 768];          // [br][i*768 + kh*256 + o]
__device__ __align__(16) float g_pp[2][NPAIR * 512];         // pooled pair embeddings
__device__ __align__(16) float g_Cp[2][NPAIR * 768];         // Cpair[p][kh*256+o]
__device__ __align__(16) float g_E[2][NPAIR * 128 * 128];    // E[p][h][j]
__device__ int              g_pIdx[256 * 128];               // friend pair idx per (b,h)
__device__ float            g_part[2][256 * 128];            // bias partials
__device__ float            g_bias[2][128];                  // conv-bias folded through linear
__device__ float            g_eout[256 * 128];               // enemy softmax output
__device__ float            g_W[3 * 64 * 128];               // manip conv weight sums
__device__ float            g_A[3 * 64 * 256];               // manip lin reduced

__device__ __forceinline__ int pair_idx(int a, int b) {
    int lo = a < b ? a : b;
    int hi = a < b ? b : a;
    return lo * 14 - (lo * (lo - 1)) / 2 + (hi - lo);
}

__device__ __forceinline__ ull splat2(float x) {
    unsigned u = __float_as_uint(x);
    return (ull)u | ((ull)u << 32);
}
__device__ __forceinline__ float2 unpack2(ull v) {
    float2 r;
    r.x = __uint_as_float((unsigned)v);
    r.y = __uint_as_float((unsigned)(v >> 32));
    return r;
}

// ---------------------------------------------------------------------------
// 1. cwT[i*768 + kh*256 + o] = cw[o,i,kh,1]   (both branches, blockIdx.y = br)
// ---------------------------------------------------------------------------
__global__ void k_cwT(const float* __restrict__ ecw, const float* __restrict__ fcw) {
    int br = blockIdx.y;
    const float* cw = br ? fcw : ecw;
    int tid = blockIdx.x * blockDim.x + threadIdx.x;
    if (tid >= 512 * 768) return;
    int i = tid / 768;
    int r = tid % 768;
    int kh = r >> 8;
    int o  = r & 255;
    g_cwT[br][tid] = cw[((o * 512 + i) * 3 + kh) * 3 + 1];
}

// ---------------------------------------------------------------------------
// 2. pp[p][i] = max(emb[t1,i], emb[t2,i])  (both branches)
// ---------------------------------------------------------------------------
__global__ void k_pp(const float* __restrict__ eemb, const float* __restrict__ femb) {
    int br = blockIdx.y;
    const float* emb = br ? femb : eemb;
    int p = blockIdx.x;
    int t1 = 0, rem = p;
    while (rem >= 14 - t1) { rem -= 14 - t1; t1++; }
    int t2 = t1 + rem;
    int i = threadIdx.x;
    g_pp[br][p * 512 + i] = fmaxf(emb[t1 * 512 + i], emb[t2 * 512 + i]);
}

// ---------------------------------------------------------------------------
// 3. Cpair[p][c] = sum_i pp[p][i] * cwT[i][c]; 3 p's per block (105 = 35*3)
// ---------------------------------------------------------------------------
__global__ void __launch_bounds__(768) k_cpair() {
    __shared__ float s[3][512];
    int br = blockIdx.y;
    int p0 = blockIdx.x * 3;
    int t = threadIdx.x;  // 768
    for (int v = t; v < 3 * 512; v += 768) s[v >> 9][v & 511] = g_pp[br][p0 * 512 + v];
    __syncthreads();
    const float* ct = g_cwT[br] + t;
    float a0 = 0.f, a1 = 0.f, a2 = 0.f;
#pragma unroll 8
    for (int i = 0; i < 512; i++) {
        float w = ct[i * 768];
        a0 += s[0][i] * w;
        a1 += s[1][i] * w;
        a2 += s[2][i] * w;
    }
    g_Cp[br][(p0 + 0) * 768 + t] = a0;
    g_Cp[br][(p0 + 1) * 768 + t] = a1;
    g_Cp[br][(p0 + 2) * 768 + t] = a2;
}

// ---------------------------------------------------------------------------
// 4. Conv bias through linear: part[o][j] = cb[o] * sum_h lin[o*128+h, j]
// ---------------------------------------------------------------------------
__global__ void k_bias1(const float* __restrict__ ecb, const float* __restrict__ elw,
                        const float* __restrict__ fcb, const float* __restrict__ flw) {
    int br = blockIdx.y;
    const float* cb  = br ? fcb : ecb;
    const float* lin = br ? flw : elw;
    int o = blockIdx.x, j = threadIdx.x;
    const float* L = lin + (o << 7) * 128 + j;
    float s = 0.f;
#pragma unroll 4
    for (int h = 0; h < 128; h++) s += L[h * 128];
    g_part[br][o * 128 + j] = cb[o] * s;
}
__global__ void k_bias2() {
    int br = blockIdx.y, j = threadIdx.x;
    float s = 0.f;
    for (int o = 0; o < 256; o++) s += g_part[br][o * 128 + j];
    g_bias[br][j] = s;
}

// ---------------------------------------------------------------------------
// 5. E-table SGEMM with packed fp32x2 FFMA.
//    grid = (128 h', 2 br).  E[p,h',j] = sum_{kh,o} Cp[p][kh*256+o] *
//    lin[(o*128 + h'+1-kh)*128 + j],   M=128(p), N=128(j), K=768, BK=16.
//    A pre-splatted into smem as (a,a) u64 pairs; B pairs read as u64 lanes.
// ---------------------------------------------------------------------------
__global__ void __launch_bounds__(256, 2) k_egemm(const float* __restrict__ elw,
                                                  const float* __restrict__ flw) {
    const int hp = blockIdx.x;
    const int br = blockIdx.y;
    const float* lin = br ? flw : elw;
    const float* Cp = g_Cp[br];

    __shared__ __align__(16) ull   As2[16][132];  // splatted A: (a,a) per p
    __shared__ __align__(16) float Bs[16][132];

    ull acc2[8][4];
#pragma unroll
    for (int i = 0; i < 8; i++)
#pragma unroll
        for (int q = 0; q < 4; q++) acc2[i][q] = 0ull;

    const int t = threadIdx.x, tx = t & 15, ty = t >> 4;

    for (int k0 = 0; k0 < 768; k0 += 16) {
        // A tile: 128p x 16k (float4 along k), stored splatted
#pragma unroll
        for (int s = 0; s < 2; s++) {
            int v = t + s * 256;
            int p = v >> 2;
            int kq = (v & 3) << 2;
            float4 a4 = make_float4(0.f, 0.f, 0.f, 0.f);
            if (p < NPAIR) a4 = *(const float4*)(Cp + p * 768 + k0 + kq);
            As2[kq + 0][p] = splat2(a4.x);
            As2[kq + 1][p] = splat2(a4.y);
            As2[kq + 2][p] = splat2(a4.z);
            As2[kq + 3][p] = splat2(a4.w);
        }
        // B tile: 16k x 128j with (kh, h') shift
#pragma unroll
        for (int s = 0; s < 2; s++) {
            int v = t + s * 256;
            int kr = v >> 5;
            int jq = (v & 31) << 2;
            int k = k0 + kr;
            int kh = k >> 8, o = k & 255;
            int h = hp + 1 - kh;
            float4 b4 = make_float4(0.f, 0.f, 0.f, 0.f);
            if ((unsigned)h < 128u) b4 = *(const float4*)(lin + ((o << 7) + h) * 128 + jq);
            *(float4*)&Bs[kr][jq] = b4;
        }
        __syncthreads();
#pragma unroll
        for (int kk = 0; kk < 16; kk++) {
            ull a2[8], b2[4];
            {
                ulonglong2 t0 = *(const ulonglong2*)&As2[kk][ty * 8 + 0];
                ulonglong2 t1 = *(const ulonglong2*)&As2[kk][ty * 8 + 2];
                ulonglong2 t2 = *(const ulonglong2*)&As2[kk][ty * 8 + 4];
                ulonglong2 t3 = *(const ulonglong2*)&As2[kk][ty * 8 + 6];
                a2[0] = t0.x; a2[1] = t0.y; a2[2] = t1.x; a2[3] = t1.y;
                a2[4] = t2.x; a2[5] = t2.y; a2[6] = t3.x; a2[7] = t3.y;
            }
            {
                ulonglong2 u0 = *(const ulonglong2*)&Bs[kk][tx * 8];
                ulonglong2 u1 = *(const ulonglong2*)&Bs[kk][tx * 8 + 4];
                b2[0] = u0.x; b2[1] = u0.y; b2[2] = u1.x; b2[3] = u1.y;
            }
#pragma unroll
            for (int i = 0; i < 8; i++)
#pragma unroll
                for (int q = 0; q < 4; q++)
                    asm("fma.rn.f32x2 %0, %1, %2, %0;"
                        : "+l"(acc2[i][q]) : "l"(a2[i]), "l"(b2[q]));
        }
        __syncthreads();
    }

    float* E = g_E[br];
#pragma unroll
    for (int i = 0; i < 8; i++) {
        int p = ty * 8 + i;
        if (p < NPAIR) {
            float* dst = E + ((p << 7) + hp) * 128 + tx * 8;
            float2 v0 = unpack2(acc2[i][0]);
            float2 v1 = unpack2(acc2[i][1]);
            float2 v2 = unpack2(acc2[i][2]);
            float2 v3 = unpack2(acc2[i][3]);
            *(float4*)dst       = make_float4(v0.x, v0.y, v1.x, v1.y);
            *(float4*)(dst + 4) = make_float4(v2.x, v2.y, v3.x, v3.y);
        }
    }
}

// ---------------------------------------------------------------------------
// 6. Enemy gather + softmax (pair idx computed inline from x)
// ---------------------------------------------------------------------------
__global__ void k_gatherE(const int* __restrict__ x, const float* __restrict__ linb) {
    int b = blockIdx.x, j = threadIdx.x;
    __shared__ int sp[128];
    __shared__ float red[128];
    sp[j] = pair_idx(x[b * 256 + 2 * j], x[b * 256 + 2 * j + 1]);
    __syncthreads();
    const float* E = g_E[0];
    float acc = g_bias[0][j] + linb[j];
#pragma unroll 4
    for (int h = 0; h < 128; h++) acc += E[((sp[h] << 7) + h) * 128 + j];

    red[j] = acc;
    __syncthreads();
    for (int s = 64; s > 0; s >>= 1) {
        if (j < s) red[j] = fmaxf(red[j], red[j + s]);
        __syncthreads();
    }
    float m = red[0];
    __syncthreads();
    float e = expf(acc - m);
    red[j] = e;
    __syncthreads();
    for (int s = 64; s > 0; s >>= 1) {
        if (j < s) red[j] += red[j + s];
        __syncthreads();
    }
    g_eout[b * 128 + j] = e / red[0];
}

// ---------------------------------------------------------------------------
// 7. Manipulator precompute
// ---------------------------------------------------------------------------
__global__ void k_wsum(const float* __restrict__ mw) {
    int tid = blockIdx.x * blockDim.x + threadIdx.x;
    if (tid >= 3 * 64 * 128) return;
    int v = tid / 8192, r = tid & 8191, o = r >> 7, i = r & 127;
    int base = ((o * 128 + i) * 3) * 3 + 1;  // (o,i,kh=0,kw=1)
    float w0 = mw[base], w1 = mw[base + 3], w2 = mw[base + 6];
    float s = (v == 0) ? (w1 + w2) : (v == 1 ? (w0 + w1 + w2) : (w0 + w1));
    g_W[tid] = s;
}

__global__ void k_areduce(const float* __restrict__ ml) {
    int o = blockIdx.x, j = threadIdx.x;
    const float* base = ml + (o << 7) * 256 + j;
    float a0 = base[0];
    float ae = base[127 * 256];
    float ai = 0.f;
#pragma unroll 4
    for (int h = 1; h < 127; h++) ai += base[h * 256];
    g_A[0 * 16384 + o * 256 + j] = a0;
    g_A[1 * 16384 + o * 256 + j] = ai;
    g_A[2 * 16384 + o * 256 + j] = ae;
}

// ---------------------------------------------------------------------------
// 8. Manipulator main + friend token/pair generation
// ---------------------------------------------------------------------------
__global__ void k_manip(const float* __restrict__ mb, const float* __restrict__ mlb) {
    int b = blockIdx.x, t = threadIdx.x;
    __shared__ float eo[128];
    __shared__ float ry[192];
    __shared__ int tok[256];
    if (t < 128) eo[t] = g_eout[b * 128 + t];
    __syncthreads();
    if (t < 192) {
        int v = t >> 6, o = t & 63;
        const float* W = g_W + v * 8192 + o * 128;
        float s = mb[o];
#pragma unroll 4
        for (int i = 0; i < 128; i++) s += eo[i] * W[i];
        ry[t] = fmaxf(s, 0.f);
    }
    __syncthreads();
    int j = t;
    float acc = mlb[j];
#pragma unroll 2
    for (int o = 0; o < 64; o++) {
        acc += ry[o]       * g_A[o * 256 + j]
             + ry[64 + o]  * g_A[16384 + o * 256 + j]
             + ry[128 + o] * g_A[32768 + o * 256 + j];
    }
    tok[j] = (int)(((long long)floorf(fabsf(acc) * 100.0f)) % 14);
    __syncthreads();
    if (t < 128) g_pIdx[b * 128 + t] = pair_idx(tok[2 * t], tok[2 * t + 1]);
}

// ---------------------------------------------------------------------------
// 9. Friend gather + head + softmax(14)   (fused)
// ---------------------------------------------------------------------------
__global__ void k_gatherF_head(const float* __restrict__ flb,
                               const float* __restrict__ L2,
                               const float* __restrict__ b2,
                               float* __restrict__ out) {
    int b = blockIdx.x, j = threadIdx.x;
    __shared__ int sp[128];
    __shared__ float f[128];
    sp[j] = g_pIdx[b * 128 + j];
    __syncthreads();
    const float* E = g_E[1];
    float acc = g_bias[1][j] + flb[j];
#pragma unroll 4
    for (int h = 0; h < 128; h++) acc += E[((sp[h] << 7) + h) * 128 + j];
    f[j] = acc;
    __syncthreads();
    if (j < 32) {
        float a = -INFINITY;
        if (j < 14) {
            a = b2[j];
#pragma unroll 4
            for (int i = 0; i < 128; i++) a += f[i] * L2[i * 14 + j];
        }
        float m = a;
        for (int off = 16; off; off >>= 1) m = fmaxf(m, __shfl_xor_sync(0xffffffffu, m, off));
        float e = (j < 14) ? expf(a - m) : 0.f;
        float s = e;
        for (int off = 16; off; off >>= 1) s += __shfl_xor_sync(0xffffffffu, s, off);
        if (j < 14) out[b * 14 + j] = e / s;
    }
}

// ---------------------------------------------------------------------------
// Launch sequence (single stream, graph-capturable)
// ---------------------------------------------------------------------------
extern "C" void kernel_launch(void* const* d_in, const int* in_sizes, int n_in,
                              void* d_out, int out_size) {
    (void)in_sizes; (void)n_in; (void)out_size;
    const int*   x    = (const int*)  d_in[0];
    const float* eemb = (const float*)d_in[1];
    const float* ecw  = (const float*)d_in[2];
    const float* ecb  = (const float*)d_in[3];
    const float* elw  = (const float*)d_in[4];
    const float* elb  = (const float*)d_in[5];
    // d_in[6] = rand_proj: dead (fog_of_war perm == arange)
    const float* mcw  = (const float*)d_in[7];
    const float* mcb  = (const float*)d_in[8];
    const float* mlw  = (const float*)d_in[9];
    const float* mlb  = (const float*)d_in[10];
    const float* femb = (const float*)d_in[11];
    const float* fcw  = (const float*)d_in[12];
    const float* fcb  = (const float*)d_in[13];
    const float* flw  = (const float*)d_in[14];
    const float* flb  = (const float*)d_in[15];
    const float* fl2w = (const float*)d_in[16];
    const float* fl2b = (const float*)d_in[17];
    float* out = (float*)d_out;

    k_cwT   <<<dim3(1536, 2), 256>>>(ecw, fcw);
    k_pp    <<<dim3(NPAIR, 2), 512>>>(eemb, femb);
    k_cpair <<<dim3(35, 2), 768>>>();
    k_bias1 <<<dim3(256, 2), 128>>>(ecb, elw, fcb, flw);
    k_bias2 <<<dim3(1, 2), 128>>>();
    k_wsum  <<<96, 256>>>(mcw);
    k_areduce<<<64, 256>>>(mlw);

    // Both branches' E tables in one launch (data-independent of tokens)
    k_egemm <<<dim3(128, 2), 256>>>(elw, flw);

    k_gatherE<<<256, 128>>>(x, elb);
    k_manip  <<<256, 256>>>(mcb, mlb);
    k_gatherF_head<<<256, 128>>>(flb, fl2w, fl2b, out);
}

// round 3
// speedup vs baseline: 1.3467x; 1.2465x over previous
#include <cuda_runtime.h>
#include <math.h>

// ---------------------------------------------------------------------------
// B=256, L=256, V=14, EMB=512, pooled length NH=128, NPAIR = C(14,2)+14 = 105
// ---------------------------------------------------------------------------
#define NPAIR 105
typedef unsigned long long ull;

// ---------------------------------------------------------------------------
// Scratch (__device__ globals; no runtime allocation)
// ---------------------------------------------------------------------------
__device__ __align__(16) float g_cwT[2][512 * 768];          // [br][i*768 + kh*256 + o]
__device__ __align__(16) float g_pp[2][NPAIR * 512];         // pooled pair embeddings
__device__ __align__(16) float g_CpP[4][2][NPAIR * 768];     // K-split partials
__device__ __align__(16) float g_Cp[2][NPAIR * 768];         // Cpair[p][kh*256+o]
__device__ __align__(16) float g_E[2][NPAIR * 128 * 128];    // E[p][h][j]
__device__ int              g_pIdx[256 * 128];               // friend pair idx per (b,h)
__device__ float            g_part[2][256 * 128];            // bias partials
__device__ float            g_bias[2][128];                  // conv-bias folded through linear
__device__ float            g_eout[256 * 128];               // enemy softmax output
__device__ float            g_W[3 * 64 * 128];               // manip conv weight sums
__device__ float            g_A[3 * 64 * 256];               // manip lin reduced

__device__ __forceinline__ int pair_idx(int a, int b) {
    int lo = a < b ? a : b;
    int hi = a < b ? b : a;
    return lo * 14 - (lo * (lo - 1)) / 2 + (hi - lo);
}

__device__ __forceinline__ ull splat2(float x) {
    unsigned u = __float_as_uint(x);
    return (ull)u | ((ull)u << 32);
}
__device__ __forceinline__ float2 unpack2(ull v) {
    float2 r;
    r.x = __uint_as_float((unsigned)v);
    r.y = __uint_as_float((unsigned)(v >> 32));
    return r;
}

// ---------------------------------------------------------------------------
// 1. Coalesced transpose: cwT[i*768 + kh*256 + o] = cw[o,i,kh,1]
//    One block per (o, br); stage cw[o] (4608 floats) in smem.
// ---------------------------------------------------------------------------
__global__ void k_cwT(const float* __restrict__ ecw, const float* __restrict__ fcw) {
    __shared__ float s[4608];
    int br = blockIdx.y;
    int o  = blockIdx.x;
    const float* src = (br ? fcw : ecw) + o * 4608;
    int t = threadIdx.x;  // 128
    for (int v = t; v < 4608; v += 128) s[v] = src[v];
    __syncthreads();
    float* dst = g_cwT[br];
    for (int v = t; v < 1536; v += 128) {
        int i = v / 3, kh = v - i * 3;
        dst[i * 768 + kh * 256 + o] = s[i * 9 + kh * 3 + 1];
    }
}

// ---------------------------------------------------------------------------
// 2. pp[p][i] = max(emb[t1,i], emb[t2,i])
// ---------------------------------------------------------------------------
__global__ void k_pp(const float* __restrict__ eemb, const float* __restrict__ femb) {
    int br = blockIdx.y;
    const float* emb = br ? femb : eemb;
    int p = blockIdx.x;
    int t1 = 0, rem = p;
    while (rem >= 14 - t1) { rem -= 14 - t1; t1++; }
    int t2 = t1 + rem;
    int i = threadIdx.x;
    g_pp[br][p * 512 + i] = fmaxf(emb[t1 * 512 + i], emb[t2 * 512 + i]);
}

// ---------------------------------------------------------------------------
// 3a. Cpair partials: K split into 4 quarters for parallelism + L2 reuse.
//     grid (35 p-triples, 2 br, 4 kq), 768 thr (c = kh*256+o).
// ---------------------------------------------------------------------------
__global__ void __launch_bounds__(768) k_cpair_ks() {
    __shared__ float s[3][128];
    int br = blockIdx.y, q = blockIdx.z;
    int p0 = blockIdx.x * 3;
    int t = threadIdx.x;
    if (t < 384) {
        int pl = t >> 7, ii = t & 127;
        s[pl][ii] = g_pp[br][(p0 + pl) * 512 + q * 128 + ii];
    }
    __syncthreads();
    const float* ct = g_cwT[br] + (q * 128) * 768 + t;
    float a0 = 0.f, a1 = 0.f, a2 = 0.f;
#pragma unroll 8
    for (int i = 0; i < 128; i++) {
        float w = ct[i * 768];
        a0 += s[0][i] * w;
        a1 += s[1][i] * w;
        a2 += s[2][i] * w;
    }
    g_CpP[q][br][(p0 + 0) * 768 + t] = a0;
    g_CpP[q][br][(p0 + 1) * 768 + t] = a1;
    g_CpP[q][br][(p0 + 2) * 768 + t] = a2;
}

// 3b. Reduce the 4 partials.
__global__ void k_cpair_red() {
    int br = blockIdx.y, p = blockIdx.x, c = threadIdx.x;
    int idx = p * 768 + c;
    g_Cp[br][idx] = (g_CpP[0][br][idx] + g_CpP[1][br][idx])
                  + (g_CpP[2][br][idx] + g_CpP[3][br][idx]);
}

// ---------------------------------------------------------------------------
// 4. Conv bias through linear: part[o][j] = cb[o] * sum_h lin[o*128+h, j]
// ---------------------------------------------------------------------------
__global__ void k_bias1(const float* __restrict__ ecb, const float* __restrict__ elw,
                        const float* __restrict__ fcb, const float* __restrict__ flw) {
    int br = blockIdx.y;
    const float* cb  = br ? fcb : ecb;
    const float* lin = br ? flw : elw;
    int o = blockIdx.x, j = threadIdx.x;
    const float* L = lin + (o << 7) * 128 + j;
    float s = 0.f;
#pragma unroll 16
    for (int h = 0; h < 128; h++) s += L[h * 128];
    g_part[br][o * 128 + j] = cb[o] * s;
}
__global__ void k_bias2() {
    int br = blockIdx.y, j = threadIdx.x;
    float s = 0.f;
#pragma unroll 8
    for (int o = 0; o < 256; o++) s += g_part[br][o * 128 + j];
    g_bias[br][j] = s;
}

// ---------------------------------------------------------------------------
// 5. E-table SGEMM, fp32x2 FFMA, broadcast-A + register splat.
//    grid = (128 h', 2 br).  E[p,h',j] = sum_{kh,o} Cp[p][kh*256+o] *
//    lin[(o*128 + h'+1-kh)*128 + j],  M=128(p), N=128(j), K=768, BK=16.
// ---------------------------------------------------------------------------
__global__ void __launch_bounds__(256, 2) k_egemm(const float* __restrict__ elw,
                                                  const float* __restrict__ flw) {
    const int hp = blockIdx.x;
    const int br = blockIdx.y;
    const float* lin = br ? flw : elw;
    const float* Cp = g_Cp[br];

    __shared__ __align__(16) float As[16][132];
    __shared__ __align__(16) float Bs[16][132];

    ull acc2[8][4];
#pragma unroll
    for (int i = 0; i < 8; i++)
#pragma unroll
        for (int q = 0; q < 4; q++) acc2[i][q] = 0ull;

    const int t = threadIdx.x, tx = t & 15, ty = t >> 4;

    for (int k0 = 0; k0 < 768; k0 += 16) {
        // A tile: 128p x 16k (float4 along k)
#pragma unroll
        for (int s = 0; s < 2; s++) {
            int v = t + s * 256;
            int p = v >> 2;
            int kq = (v & 3) << 2;
            float4 a4 = make_float4(0.f, 0.f, 0.f, 0.f);
            if (p < NPAIR) a4 = *(const float4*)(Cp + p * 768 + k0 + kq);
            As[kq + 0][p] = a4.x;
            As[kq + 1][p] = a4.y;
            As[kq + 2][p] = a4.z;
            As[kq + 3][p] = a4.w;
        }
        // B tile: 16k x 128j with (kh, h') shift
#pragma unroll
        for (int s = 0; s < 2; s++) {
            int v = t + s * 256;
            int kr = v >> 5;
            int jq = (v & 31) << 2;
            int k = k0 + kr;
            int kh = k >> 8, o = k & 255;
            int h = hp + 1 - kh;
            float4 b4 = make_float4(0.f, 0.f, 0.f, 0.f);
            if ((unsigned)h < 128u) b4 = *(const float4*)(lin + ((o << 7) + h) * 128 + jq);
            *(float4*)&Bs[kr][jq] = b4;
        }
        __syncthreads();
#pragma unroll
        for (int kk = 0; kk < 16; kk++) {
            // A: 2 broadcast LDS.128 (only 2 distinct addrs per warp), splat in regs
            float4 af0 = *(const float4*)&As[kk][ty * 8];
            float4 af1 = *(const float4*)&As[kk][ty * 8 + 4];
            // B: 2 LDS.128 read directly as u64 pairs
            ulonglong2 u0 = *(const ulonglong2*)&Bs[kk][tx * 8];
            ulonglong2 u1 = *(const ulonglong2*)&Bs[kk][tx * 8 + 4];
            ull b2[4] = {u0.x, u0.y, u1.x, u1.y};
            ull a2[8];
            a2[0] = splat2(af0.x); a2[1] = splat2(af0.y);
            a2[2] = splat2(af0.z); a2[3] = splat2(af0.w);
            a2[4] = splat2(af1.x); a2[5] = splat2(af1.y);
            a2[6] = splat2(af1.z); a2[7] = splat2(af1.w);
#pragma unroll
            for (int i = 0; i < 8; i++)
#pragma unroll
                for (int q = 0; q < 4; q++)
                    asm("fma.rn.f32x2 %0, %1, %2, %0;"
                        : "+l"(acc2[i][q]) : "l"(a2[i]), "l"(b2[q]));
        }
        __syncthreads();
    }

    float* E = g_E[br];
#pragma unroll
    for (int i = 0; i < 8; i++) {
        int p = ty * 8 + i;
        if (p < NPAIR) {
            float* dst = E + ((p << 7) + hp) * 128 + tx * 8;
            float2 v0 = unpack2(acc2[i][0]);
            float2 v1 = unpack2(acc2[i][1]);
            float2 v2 = unpack2(acc2[i][2]);
            float2 v3 = unpack2(acc2[i][3]);
            *(float4*)dst       = make_float4(v0.x, v0.y, v1.x, v1.y);
            *(float4*)(dst + 4) = make_float4(v2.x, v2.y, v3.x, v3.y);
        }
    }
}

// ---------------------------------------------------------------------------
// 6. Enemy gather + softmax
// ---------------------------------------------------------------------------
__global__ void k_gatherE(const int* __restrict__ x, const float* __restrict__ linb) {
    int b = blockIdx.x, j = threadIdx.x;
    __shared__ int sp[128];
    __shared__ float red[128];
    sp[j] = pair_idx(x[b * 256 + 2 * j], x[b * 256 + 2 * j + 1]);
    __syncthreads();
    const float* E = g_E[0];
    float acc = g_bias[0][j] + linb[j];
#pragma unroll 4
    for (int h = 0; h < 128; h++) acc += E[((sp[h] << 7) + h) * 128 + j];

    red[j] = acc;
    __syncthreads();
    for (int s = 64; s > 0; s >>= 1) {
        if (j < s) red[j] = fmaxf(red[j], red[j + s]);
        __syncthreads();
    }
    float m = red[0];
    __syncthreads();
    float e = expf(acc - m);
    red[j] = e;
    __syncthreads();
    for (int s = 64; s > 0; s >>= 1) {
        if (j < s) red[j] += red[j + s];
        __syncthreads();
    }
    g_eout[b * 128 + j] = e / red[0];
}

// ---------------------------------------------------------------------------
// 7. Manipulator precompute
// ---------------------------------------------------------------------------
__global__ void k_wsum(const float* __restrict__ mw) {
    int tid = blockIdx.x * blockDim.x + threadIdx.x;
    if (tid >= 3 * 64 * 128) return;
    int v = tid / 8192, r = tid & 8191, o = r >> 7, i = r & 127;
    int base = ((o * 128 + i) * 3) * 3 + 1;  // (o,i,kh=0,kw=1)
    float w0 = mw[base], w1 = mw[base + 3], w2 = mw[base + 6];
    float s = (v == 0) ? (w1 + w2) : (v == 1 ? (w0 + w1 + w2) : (w0 + w1));
    g_W[tid] = s;
}

__global__ void k_areduce(const float* __restrict__ ml) {
    int o = blockIdx.x, j = threadIdx.x;
    const float* base = ml + (o << 7) * 256 + j;
    float a0 = base[0];
    float ae = base[127 * 256];
    float ai = 0.f;
#pragma unroll 16
    for (int h = 1; h < 127; h++) ai += base[h * 256];
    g_A[0 * 16384 + o * 256 + j] = a0;
    g_A[1 * 16384 + o * 256 + j] = ai;
    g_A[2 * 16384 + o * 256 + j] = ae;
}

// ---------------------------------------------------------------------------
// 8. Manipulator main + friend token/pair generation (2 batches per block)
// ---------------------------------------------------------------------------
__global__ void k_manip(const float* __restrict__ mb, const float* __restrict__ mlb) {
    int b0 = blockIdx.x * 2;
    int t = threadIdx.x;  // 256
    __shared__ float eo[2][128];
    __shared__ float ry[2][192];
    __shared__ int tok[2][256];
    eo[t >> 7][t & 127] = g_eout[(b0 + (t >> 7)) * 128 + (t & 127)];
    __syncthreads();
    if (t < 192) {
        int v = t >> 6, o = t & 63;
        const float* W = g_W + v * 8192 + o * 128;
        float base = mb[o];
        float s0 = base, s1 = base;
#pragma unroll 4
        for (int i = 0; i < 128; i++) {
            float w = W[i];
            s0 += eo[0][i] * w;
            s1 += eo[1][i] * w;
        }
        ry[0][t] = fmaxf(s0, 0.f);
        ry[1][t] = fmaxf(s1, 0.f);
    }
    __syncthreads();
    int j = t;
    float base = mlb[j];
    float acc0 = base, acc1 = base;
#pragma unroll 2
    for (int o = 0; o < 64; o++) {
        float a0 = g_A[o * 256 + j];
        float a1 = g_A[16384 + o * 256 + j];
        float a2 = g_A[32768 + o * 256 + j];
        acc0 += ry[0][o] * a0 + ry[0][64 + o] * a1 + ry[0][128 + o] * a2;
        acc1 += ry[1][o] * a0 + ry[1][64 + o] * a1 + ry[1][128 + o] * a2;
    }
    tok[0][j] = (int)(((long long)floorf(fabsf(acc0) * 100.0f)) % 14);
    tok[1][j] = (int)(((long long)floorf(fabsf(acc1) * 100.0f)) % 14);
    __syncthreads();
    {
        int bb = t >> 7, h = t & 127;
        g_pIdx[(b0 + bb) * 128 + h] = pair_idx(tok[bb][2 * h], tok[bb][2 * h + 1]);
    }
}

// ---------------------------------------------------------------------------
// 9. Friend gather + head + softmax(14)
// ---------------------------------------------------------------------------
__global__ void k_gatherF_head(const float* __restrict__ flb,
                               const float* __restrict__ L2,
                               const float* __restrict__ b2,
                               float* __restrict__ out) {
    int b = blockIdx.x, j = threadIdx.x;
    __shared__ int sp[128];
    __shared__ float f[128];
    sp[j] = g_pIdx[b * 128 + j];
    __syncthreads();
    const float* E = g_E[1];
    float acc = g_bias[1][j] + flb[j];
#pragma unroll 4
    for (int h = 0; h < 128; h++) acc += E[((sp[h] << 7) + h) * 128 + j];
    f[j] = acc;
    __syncthreads();
    if (j < 32) {
        float a = -INFINITY;
        if (j < 14) {
            a = b2[j];
#pragma unroll 4
            for (int i = 0; i < 128; i++) a += f[i] * L2[i * 14 + j];
        }
        float m = a;
        for (int off = 16; off; off >>= 1) m = fmaxf(m, __shfl_xor_sync(0xffffffffu, m, off));
        float e = (j < 14) ? expf(a - m) : 0.f;
        float s = e;
        for (int off = 16; off; off >>= 1) s += __shfl_xor_sync(0xffffffffu, s, off);
        if (j < 14) out[b * 14 + j] = e / s;
    }
}

// ---------------------------------------------------------------------------
// Launch sequence (single stream, graph-capturable)
// ---------------------------------------------------------------------------
extern "C" void kernel_launch(void* const* d_in, const int* in_sizes, int n_in,
                              void* d_out, int out_size) {
    (void)in_sizes; (void)n_in; (void)out_size;
    const int*   x    = (const int*)  d_in[0];
    const float* eemb = (const float*)d_in[1];
    const float* ecw  = (const float*)d_in[2];
    const float* ecb  = (const float*)d_in[3];
    const float* elw  = (const float*)d_in[4];
    const float* elb  = (const float*)d_in[5];
    // d_in[6] = rand_proj: dead (fog_of_war perm == arange)
    const float* mcw  = (const float*)d_in[7];
    const float* mcb  = (const float*)d_in[8];
    const float* mlw  = (const float*)d_in[9];
    const float* mlb  = (const float*)d_in[10];
    const float* femb = (const float*)d_in[11];
    const float* fcw  = (const float*)d_in[12];
    const float* fcb  = (const float*)d_in[13];
    const float* flw  = (const float*)d_in[14];
    const float* flb  = (const float*)d_in[15];
    const float* fl2w = (const float*)d_in[16];
    const float* fl2b = (const float*)d_in[17];
    float* out = (float*)d_out;

    k_cwT      <<<dim3(256, 2), 128>>>(ecw, fcw);
    k_pp       <<<dim3(NPAIR, 2), 512>>>(eemb, femb);
    k_cpair_ks <<<dim3(35, 2, 4), 768>>>();
    k_cpair_red<<<dim3(NPAIR, 2), 768>>>();
    k_bias1    <<<dim3(256, 2), 128>>>(ecb, elw, fcb, flw);
    k_bias2    <<<dim3(1, 2), 128>>>();
    k_wsum     <<<96, 256>>>(mcw);
    k_areduce  <<<64, 256>>>(mlw);

    // Both branches' E tables in one launch (data-independent of tokens)
    k_egemm <<<dim3(128, 2), 256>>>(elw, flw);

    k_gatherE<<<256, 128>>>(x, elb);
    k_manip  <<<128, 256>>>(mcb, mlb);
    k_gatherF_head<<<256, 128>>>(flb, fl2w, fl2b, out);
}